// round 2
// baseline (speedup 1.0000x reference)
#include <cuda_runtime.h>
#include <cstdio>

#define L_SEQ 4096
#define D_MODEL 768
#define NUM_HEADS 12
#define D_K 64

// Scratch (device globals: allocation-free per harness rules)
__device__ float g_qp[L_SEQ * D_MODEL];
__device__ float g_kp[L_SEQ * D_MODEL];
__device__ float g_vp[L_SEQ * D_MODEL];
__device__ float g_att[L_SEQ * D_MODEL];

// ---------------------------------------------------------------------------
// GEMM with bias: C[M,768] = A[M,768] @ W^T + b   (W row-major [768,768])
// BM=128, BN=128, BK=16, 256 threads (16x16), 8x8 per-thread tile.
// Both A and W are K-major (NT gemm) -> coalesced global loads.
// ---------------------------------------------------------------------------
__global__ __launch_bounds__(256) void gemm_bias_kernel(
    const float* __restrict__ A, const float* __restrict__ W,
    const float* __restrict__ bias, float* __restrict__ C)
{
    __shared__ float As[16][128];   // [k][m]
    __shared__ float Ws[16][128];   // [k][n]

    const int tx = threadIdx.x, ty = threadIdx.y;
    const int tid = ty * 16 + tx;
    const int m0 = blockIdx.y * 128;
    const int n0 = blockIdx.x * 128;

    float acc[8][8];
#pragma unroll
    for (int i = 0; i < 8; i++)
#pragma unroll
        for (int j = 0; j < 8; j++) acc[i][j] = 0.f;

    for (int kt = 0; kt < D_MODEL / 16; kt++) {
        __syncthreads();
#pragma unroll
        for (int p = 0; p < 2; p++) {
            int f = tid + p * 256;
            int row = f >> 2;
            int c4 = (f & 3) << 2;
            float4 a = *(const float4*)(A + (size_t)(m0 + row) * D_MODEL + kt * 16 + c4);
            As[c4 + 0][row] = a.x; As[c4 + 1][row] = a.y;
            As[c4 + 2][row] = a.z; As[c4 + 3][row] = a.w;
            float4 w = *(const float4*)(W + (size_t)(n0 + row) * D_MODEL + kt * 16 + c4);
            Ws[c4 + 0][row] = w.x; Ws[c4 + 1][row] = w.y;
            Ws[c4 + 2][row] = w.z; Ws[c4 + 3][row] = w.w;
        }
        __syncthreads();

#pragma unroll
        for (int kk = 0; kk < 16; kk++) {
            float4 a0 = *(const float4*)(&As[kk][ty * 8]);
            float4 a1 = *(const float4*)(&As[kk][ty * 8 + 4]);
            float4 w0 = *(const float4*)(&Ws[kk][tx * 8]);
            float4 w1 = *(const float4*)(&Ws[kk][tx * 8 + 4]);
            float ar[8] = {a0.x, a0.y, a0.z, a0.w, a1.x, a1.y, a1.z, a1.w};
            float wr[8] = {w0.x, w0.y, w0.z, w0.w, w1.x, w1.y, w1.z, w1.w};
#pragma unroll
            for (int i = 0; i < 8; i++)
#pragma unroll
                for (int j = 0; j < 8; j++) acc[i][j] += ar[i] * wr[j];
        }
    }

#pragma unroll
    for (int i = 0; i < 8; i++) {
        int row = m0 + ty * 8 + i;
        int col = n0 + tx * 8;
        float4 b0 = *(const float4*)(bias + col);
        float4 b1 = *(const float4*)(bias + col + 4);
        float4 o0 = make_float4(acc[i][0] + b0.x, acc[i][1] + b0.y,
                                acc[i][2] + b0.z, acc[i][3] + b0.w);
        float4 o1 = make_float4(acc[i][4] + b1.x, acc[i][5] + b1.y,
                                acc[i][6] + b1.z, acc[i][7] + b1.w);
        *(float4*)(C + (size_t)row * D_MODEL + col) = o0;
        *(float4*)(C + (size_t)row * D_MODEL + col + 4) = o1;
    }
}

// ---------------------------------------------------------------------------
// Flash attention: per (q-tile of 128, head). 64-key tiles, online softmax.
// 256 threads (16x16): thread owns rows ty*8..+7 (queries), cols tx*4..+3
// (keys in S, head-dims in O). Scale 1/sqrt(64) folded into Q on load.
// ---------------------------------------------------------------------------
#define Q_SMEM (64 * 128)        // [d][row]
#define K_SMEM (64 * 64)         // [d][key]
#define V_SMEM (64 * 64)         // [key][d]
#define P_SMEM (128 * 68)        // [row][key], pad 4
#define FLASH_SMEM_BYTES ((Q_SMEM + K_SMEM + V_SMEM + P_SMEM) * 4)

__global__ __launch_bounds__(256) void flash_attn_kernel(
    const float* __restrict__ qp, const float* __restrict__ kp,
    const float* __restrict__ vp, float* __restrict__ att)
{
    extern __shared__ float sm[];
    float* Qs = sm;                    // [64][128]
    float* Ks = Qs + Q_SMEM;           // [64][64]
    float* Vs = Ks + K_SMEM;           // [64][64]
    float* Ps = Vs + V_SMEM;           // [128][68]

    const int tx = threadIdx.x, ty = threadIdx.y;
    const int tid = ty * 16 + tx;
    const int h = blockIdx.y;
    const int q0 = blockIdx.x * 128;
    const int hoff = h * D_K;
    const float scale = 0.125f;        // 1/sqrt(64)

    // Load Q tile transposed [d][row], pre-scaled
#pragma unroll
    for (int p = 0; p < 8; p++) {
        int f = tid + p * 256;
        int row = f >> 4;
        int c4 = (f & 15) << 2;
        float4 v = *(const float4*)(qp + (size_t)(q0 + row) * D_MODEL + hoff + c4);
        Qs[(c4 + 0) * 128 + row] = v.x * scale;
        Qs[(c4 + 1) * 128 + row] = v.y * scale;
        Qs[(c4 + 2) * 128 + row] = v.z * scale;
        Qs[(c4 + 3) * 128 + row] = v.w * scale;
    }

    float m[8], l[8], o[8][4];
#pragma unroll
    for (int i = 0; i < 8; i++) {
        m[i] = -1e30f; l[i] = 0.f;
        o[i][0] = o[i][1] = o[i][2] = o[i][3] = 0.f;
    }

    for (int kt = 0; kt < L_SEQ / 64; kt++) {
        __syncthreads();   // protect Ks/Vs (prev S-gemm/PV done) and Qs on iter 0
        const int k0 = kt * 64;
#pragma unroll
        for (int p = 0; p < 4; p++) {
            int f = tid + p * 256;
            int row = f >> 4;
            int c4 = (f & 15) << 2;
            float4 kv = *(const float4*)(kp + (size_t)(k0 + row) * D_MODEL + hoff + c4);
            Ks[(c4 + 0) * 64 + row] = kv.x;
            Ks[(c4 + 1) * 64 + row] = kv.y;
            Ks[(c4 + 2) * 64 + row] = kv.z;
            Ks[(c4 + 3) * 64 + row] = kv.w;
            float4 vv = *(const float4*)(vp + (size_t)(k0 + row) * D_MODEL + hoff + c4);
            *(float4*)(Vs + row * 64 + c4) = vv;
        }
        __syncthreads();

        // S = Q @ K^T (scaled)
        float s[8][4];
#pragma unroll
        for (int i = 0; i < 8; i++) { s[i][0] = s[i][1] = s[i][2] = s[i][3] = 0.f; }
#pragma unroll
        for (int kk = 0; kk < 64; kk++) {
            float4 qa = *(const float4*)(Qs + kk * 128 + ty * 8);
            float4 qb = *(const float4*)(Qs + kk * 128 + ty * 8 + 4);
            float4 kf = *(const float4*)(Ks + kk * 64 + tx * 4);
            float qr[8] = {qa.x, qa.y, qa.z, qa.w, qb.x, qb.y, qb.z, qb.w};
#pragma unroll
            for (int i = 0; i < 8; i++) {
                s[i][0] += qr[i] * kf.x;
                s[i][1] += qr[i] * kf.y;
                s[i][2] += qr[i] * kf.z;
                s[i][3] += qr[i] * kf.w;
            }
        }

        // Online softmax update + write P
#pragma unroll
        for (int i = 0; i < 8; i++) {
            float rmax = fmaxf(fmaxf(s[i][0], s[i][1]), fmaxf(s[i][2], s[i][3]));
#pragma unroll
            for (int off = 8; off >= 1; off >>= 1)
                rmax = fmaxf(rmax, __shfl_xor_sync(0xffffffffu, rmax, off));
            float mnew = fmaxf(m[i], rmax);
            float corr = __expf(m[i] - mnew);
            float p0 = __expf(s[i][0] - mnew);
            float p1 = __expf(s[i][1] - mnew);
            float p2 = __expf(s[i][2] - mnew);
            float p3 = __expf(s[i][3] - mnew);
            float rsum = p0 + p1 + p2 + p3;
#pragma unroll
            for (int off = 8; off >= 1; off >>= 1)
                rsum += __shfl_xor_sync(0xffffffffu, rsum, off);
            l[i] = l[i] * corr + rsum;
            m[i] = mnew;
            o[i][0] *= corr; o[i][1] *= corr; o[i][2] *= corr; o[i][3] *= corr;
            float4 pv = make_float4(p0, p1, p2, p3);
            *(float4*)(Ps + (ty * 8 + i) * 68 + tx * 4) = pv;
        }
        __syncthreads();

        // O += P @ V
#pragma unroll
        for (int k4 = 0; k4 < 16; k4++) {
            float4 v0 = *(const float4*)(Vs + (k4 * 4 + 0) * 64 + tx * 4);
            float4 v1 = *(const float4*)(Vs + (k4 * 4 + 1) * 64 + tx * 4);
            float4 v2 = *(const float4*)(Vs + (k4 * 4 + 2) * 64 + tx * 4);
            float4 v3 = *(const float4*)(Vs + (k4 * 4 + 3) * 64 + tx * 4);
#pragma unroll
            for (int i = 0; i < 8; i++) {
                float4 p4 = *(const float4*)(Ps + (ty * 8 + i) * 68 + k4 * 4);
                o[i][0] += p4.x * v0.x + p4.y * v1.x + p4.z * v2.x + p4.w * v3.x;
                o[i][1] += p4.x * v0.y + p4.y * v1.y + p4.z * v2.y + p4.w * v3.y;
                o[i][2] += p4.x * v0.z + p4.y * v1.z + p4.z * v2.z + p4.w * v3.z;
                o[i][3] += p4.x * v0.w + p4.y * v1.w + p4.z * v2.w + p4.w * v3.w;
            }
        }
    }

    // Epilogue: normalize and write attention output (merged heads layout)
#pragma unroll
    for (int i = 0; i < 8; i++) {
        float inv = 1.f / l[i];
        float4 out = make_float4(o[i][0] * inv, o[i][1] * inv,
                                 o[i][2] * inv, o[i][3] * inv);
        *(float4*)(att + (size_t)(q0 + ty * 8 + i) * D_MODEL + hoff + tx * 4) = out;
    }
}

// ---------------------------------------------------------------------------
extern "C" void kernel_launch(void* const* d_in, const int* in_sizes, int n_in,
                              void* d_out, int out_size)
{
    const float* q  = (const float*)d_in[0];
    const float* k  = (const float*)d_in[1];
    const float* v  = (const float*)d_in[2];
    const float* Wq = (const float*)d_in[3];
    const float* bq = (const float*)d_in[4];
    const float* Wk = (const float*)d_in[5];
    const float* bk = (const float*)d_in[6];
    const float* Wv = (const float*)d_in[7];
    const float* bv = (const float*)d_in[8];
    const float* Wo = (const float*)d_in[9];
    const float* bo = (const float*)d_in[10];
    float* out = (float*)d_out;

    float *p_qp, *p_kp, *p_vp, *p_att;
    cudaGetSymbolAddress((void**)&p_qp,  g_qp);
    cudaGetSymbolAddress((void**)&p_kp,  g_kp);
    cudaGetSymbolAddress((void**)&p_vp,  g_vp);
    cudaGetSymbolAddress((void**)&p_att, g_att);

    static bool attr_set = false;
    if (!attr_set) {
        cudaFuncSetAttribute(flash_attn_kernel,
                             cudaFuncAttributeMaxDynamicSharedMemorySize,
                             FLASH_SMEM_BYTES);
        attr_set = true;
    }

    dim3 gblock(16, 16);
    dim3 ggrid(D_MODEL / 128, L_SEQ / 128);   // (6, 32)

    gemm_bias_kernel<<<ggrid, gblock>>>(q, Wq, bq, p_qp);
    gemm_bias_kernel<<<ggrid, gblock>>>(k, Wk, bk, p_kp);
    gemm_bias_kernel<<<ggrid, gblock>>>(v, Wv, bv, p_vp);

    dim3 fgrid(L_SEQ / 128, NUM_HEADS);       // (32, 12)
    flash_attn_kernel<<<fgrid, gblock, FLASH_SMEM_BYTES>>>(p_qp, p_kp, p_vp, p_att);

    gemm_bias_kernel<<<ggrid, gblock>>>(p_att, Wo, bo, out);
}

// round 3
// speedup vs baseline: 2.4236x; 2.4236x over previous
#include <cuda_runtime.h>
#include <cuda_bf16.h>

#define L_SEQ 4096
#define DM 768
#define NH 12
#define DK 64

typedef unsigned int u32;

// ---------------------------------------------------------------------------
// Device scratch (bf16 hi/lo split arrays)
// ---------------------------------------------------------------------------
__device__ __nv_bfloat16 g_inq_h[L_SEQ * DM], g_inq_l[L_SEQ * DM];
__device__ __nv_bfloat16 g_ink_h[L_SEQ * DM], g_ink_l[L_SEQ * DM];
__device__ __nv_bfloat16 g_inv_h[L_SEQ * DM], g_inv_l[L_SEQ * DM];
__device__ __nv_bfloat16 g_wq_h[DM * DM], g_wq_l[DM * DM];
__device__ __nv_bfloat16 g_wk_h[DM * DM], g_wk_l[DM * DM];
__device__ __nv_bfloat16 g_wv_h[DM * DM], g_wv_l[DM * DM];
__device__ __nv_bfloat16 g_wo_h[DM * DM], g_wo_l[DM * DM];
__device__ __nv_bfloat16 g_qp_h[L_SEQ * DM], g_qp_l[L_SEQ * DM];
__device__ __nv_bfloat16 g_kp_h[L_SEQ * DM], g_kp_l[L_SEQ * DM];
__device__ __nv_bfloat16 g_vt_h[L_SEQ * DM], g_vt_l[L_SEQ * DM];   // [h][d][key]
__device__ __nv_bfloat16 g_att_h[L_SEQ * DM], g_att_l[L_SEQ * DM];

// ---------------------------------------------------------------------------
// Helpers
// ---------------------------------------------------------------------------
struct HL { u32 h, l; };

// split pair (x -> low half / even col, y -> high half / odd col)
__device__ __forceinline__ HL split2(float x, float y) {
    __nv_bfloat162 hb = __floats2bfloat162_rn(x, y);
    float2 hf = __bfloat1622float2(hb);
    __nv_bfloat162 lb = __floats2bfloat162_rn(x - hf.x, y - hf.y);
    HL r;
    r.h = *reinterpret_cast<u32*>(&hb);
    r.l = *reinterpret_cast<u32*>(&lb);
    return r;
}

__device__ __forceinline__ void split1(float v, __nv_bfloat16* ph, __nv_bfloat16* pl) {
    __nv_bfloat16 hb = __float2bfloat16_rn(v);
    *ph = hb;
    *pl = __float2bfloat16_rn(v - __bfloat162float(hb));
}

#define MMA_BF16(D, A, B) asm volatile( \
    "mma.sync.aligned.m16n8k16.row.col.f32.bf16.bf16.f32 " \
    "{%0,%1,%2,%3},{%4,%5,%6,%7},{%8,%9},{%0,%1,%2,%3};\n" \
    : "+f"((D)[0]), "+f"((D)[1]), "+f"((D)[2]), "+f"((D)[3]) \
    : "r"((A)[0]), "r"((A)[1]), "r"((A)[2]), "r"((A)[3]), \
      "r"((B)[0]), "r"((B)[1]))

// ---------------------------------------------------------------------------
// fp32 -> bf16 hi/lo split (elementwise)
// ---------------------------------------------------------------------------
__global__ void convert_split_kernel(const float* __restrict__ src,
                                     __nv_bfloat16* __restrict__ dh,
                                     __nv_bfloat16* __restrict__ dl, int n)
{
    int i = (blockIdx.x * blockDim.x + threadIdx.x) * 4;
    if (i >= n) return;
    float4 x = *(const float4*)(src + i);
    HL a = split2(x.x, x.y);
    HL b = split2(x.z, x.w);
    *(uint2*)(dh + i) = make_uint2(a.h, b.h);
    *(uint2*)(dl + i) = make_uint2(a.l, b.l);
}

// ---------------------------------------------------------------------------
// GEMM: C[M,768] = A[M,768] @ W^T + b, bf16-split 3-pass MMA, fp32 accum.
// BM=128, BN=128, BK=32, 256 thr (8 warps, 4x2), warp tile 32x64.
// MODE 0: fp32 out.  MODE 1: bf16 hi/lo out.  MODE 2: bf16 hi/lo, per-head
// transposed out [h][d][m] (for V).
// ---------------------------------------------------------------------------
template <int MODE>
__global__ __launch_bounds__(256, 2) void gemm_mma_kernel(
    const __nv_bfloat16* __restrict__ Ah, const __nv_bfloat16* __restrict__ Al,
    const __nv_bfloat16* __restrict__ Wh, const __nv_bfloat16* __restrict__ Wl,
    const float* __restrict__ bias,
    float* __restrict__ Cf,
    __nv_bfloat16* __restrict__ Ch, __nv_bfloat16* __restrict__ Cl)
{
    __shared__ __nv_bfloat16 AsH[128 * 40], AsL[128 * 40];
    __shared__ __nv_bfloat16 WsH[128 * 40], WsL[128 * 40];

    const int tid = threadIdx.x;
    const int lane = tid & 31;
    const int w = tid >> 5;
    const int wm = w >> 1, wn = w & 1;
    const int mb0 = wm * 32;
    const int nb0 = wn * 64;
    const int g = lane >> 2, t = lane & 3;

    const int m0 = blockIdx.y * 128;
    const int n0 = blockIdx.x * 128;

    float acc[2][8][4];
#pragma unroll
    for (int mi = 0; mi < 2; mi++)
#pragma unroll
        for (int ni = 0; ni < 8; ni++)
#pragma unroll
            for (int j = 0; j < 4; j++) acc[mi][ni][j] = 0.f;

    for (int kt = 0; kt < DM / 32; kt++) {
        __syncthreads();
        const __nv_bfloat16* aH = Ah + (size_t)m0 * DM + kt * 32;
        const __nv_bfloat16* aL = Al + (size_t)m0 * DM + kt * 32;
        const __nv_bfloat16* wH = Wh + (size_t)n0 * DM + kt * 32;
        const __nv_bfloat16* wL = Wl + (size_t)n0 * DM + kt * 32;
#pragma unroll
        for (int p = 0; p < 2; p++) {
            int f = tid + p * 256;
            int r = f >> 2;
            int c8 = (f & 3) * 8;
            *(uint4*)&AsH[r * 40 + c8] = *(const uint4*)&aH[(size_t)r * DM + c8];
            *(uint4*)&AsL[r * 40 + c8] = *(const uint4*)&aL[(size_t)r * DM + c8];
            *(uint4*)&WsH[r * 40 + c8] = *(const uint4*)&wH[(size_t)r * DM + c8];
            *(uint4*)&WsL[r * 40 + c8] = *(const uint4*)&wL[(size_t)r * DM + c8];
        }
        __syncthreads();

#pragma unroll
        for (int kk = 0; kk < 2; kk++) {
            const int k0 = kk * 16;
            u32 ah[2][4], al[2][4];
#pragma unroll
            for (int mi = 0; mi < 2; mi++) {
                const __nv_bfloat16* pH = &AsH[(mb0 + mi * 16 + g) * 40 + k0 + 2 * t];
                const __nv_bfloat16* pL = &AsL[(mb0 + mi * 16 + g) * 40 + k0 + 2 * t];
                ah[mi][0] = *(const u32*)pH;
                ah[mi][1] = *(const u32*)(pH + 8 * 40);
                ah[mi][2] = *(const u32*)(pH + 8);
                ah[mi][3] = *(const u32*)(pH + 8 * 40 + 8);
                al[mi][0] = *(const u32*)pL;
                al[mi][1] = *(const u32*)(pL + 8 * 40);
                al[mi][2] = *(const u32*)(pL + 8);
                al[mi][3] = *(const u32*)(pL + 8 * 40 + 8);
            }
#pragma unroll
            for (int ni = 0; ni < 8; ni++) {
                const __nv_bfloat16* bH = &WsH[(nb0 + ni * 8 + g) * 40 + k0 + 2 * t];
                const __nv_bfloat16* bL = &WsL[(nb0 + ni * 8 + g) * 40 + k0 + 2 * t];
                u32 bh[2] = { *(const u32*)bH, *(const u32*)(bH + 8) };
                u32 bl[2] = { *(const u32*)bL, *(const u32*)(bL + 8) };
#pragma unroll
                for (int mi = 0; mi < 2; mi++) {
                    MMA_BF16(acc[mi][ni], ah[mi], bh);
                    MMA_BF16(acc[mi][ni], ah[mi], bl);
                    MMA_BF16(acc[mi][ni], al[mi], bh);
                }
            }
        }
    }

    // Epilogue
#pragma unroll
    for (int mi = 0; mi < 2; mi++) {
#pragma unroll
        for (int ni = 0; ni < 8; ni++) {
            int mg = m0 + mb0 + mi * 16 + g;
            int ng = n0 + nb0 + ni * 8 + 2 * t;
            float b0 = bias[ng], b1 = bias[ng + 1];
            float c0 = acc[mi][ni][0] + b0, c1 = acc[mi][ni][1] + b1;
            float c2 = acc[mi][ni][2] + b0, c3 = acc[mi][ni][3] + b1;
            if (MODE == 0) {
                *(float2*)&Cf[(size_t)mg * DM + ng] = make_float2(c0, c1);
                *(float2*)&Cf[(size_t)(mg + 8) * DM + ng] = make_float2(c2, c3);
            } else if (MODE == 1) {
                HL x = split2(c0, c1);
                *(u32*)&Ch[(size_t)mg * DM + ng] = x.h;
                *(u32*)&Cl[(size_t)mg * DM + ng] = x.l;
                HL y = split2(c2, c3);
                *(u32*)&Ch[(size_t)(mg + 8) * DM + ng] = y.h;
                *(u32*)&Cl[(size_t)(mg + 8) * DM + ng] = y.l;
            } else {
                int hh = ng >> 6, dd = ng & 63;
                size_t base = (size_t)hh * (DK * L_SEQ) + (size_t)dd * L_SEQ;
                split1(c0, &Ch[base + mg], &Cl[base + mg]);
                split1(c1, &Ch[base + L_SEQ + mg], &Cl[base + L_SEQ + mg]);
                split1(c2, &Ch[base + mg + 8], &Cl[base + mg + 8]);
                split1(c3, &Ch[base + L_SEQ + mg + 8], &Cl[base + L_SEQ + mg + 8]);
            }
        }
    }
}

// ---------------------------------------------------------------------------
// Flash attention, bf16-split 3-pass MMA. Br=128 q rows, Bc=64 keys,
// 8 warps: warp w owns query rows 16w..16w+15.
// ---------------------------------------------------------------------------
#define PIT 72
#define OFF_QH 0
#define OFF_QL (128 * PIT)
#define OFF_KH (2 * 128 * PIT)
#define OFF_KL (2 * 128 * PIT + 64 * PIT)
#define OFF_VH (2 * 128 * PIT + 2 * 64 * PIT)
#define OFF_VL (2 * 128 * PIT + 3 * 64 * PIT)
#define OFF_PH (2 * 128 * PIT + 4 * 64 * PIT)
#define OFF_PL (3 * 128 * PIT + 4 * 64 * PIT)
#define FLASH_SMEM_ELEMS (4 * 128 * PIT + 4 * 64 * PIT)
#define FLASH_SMEM_BYTES (FLASH_SMEM_ELEMS * 2)

__global__ __launch_bounds__(256, 2) void flash_mma_kernel(
    const __nv_bfloat16* __restrict__ Qh_g, const __nv_bfloat16* __restrict__ Ql_g,
    const __nv_bfloat16* __restrict__ Kh_g, const __nv_bfloat16* __restrict__ Kl_g,
    const __nv_bfloat16* __restrict__ Vh_g, const __nv_bfloat16* __restrict__ Vl_g,
    __nv_bfloat16* __restrict__ Oh_g, __nv_bfloat16* __restrict__ Ol_g)
{
    extern __shared__ __nv_bfloat16 sm[];
    __nv_bfloat16* Qsh = sm + OFF_QH;
    __nv_bfloat16* Qsl = sm + OFF_QL;
    __nv_bfloat16* Ksh = sm + OFF_KH;
    __nv_bfloat16* Ksl = sm + OFF_KL;
    __nv_bfloat16* Vsh = sm + OFF_VH;
    __nv_bfloat16* Vsl = sm + OFF_VL;
    __nv_bfloat16* Psh = sm + OFF_PH;
    __nv_bfloat16* Psl = sm + OFF_PL;

    const int tid = threadIdx.x;
    const int lane = tid & 31;
    const int w = tid >> 5;
    const int mb = w * 16;
    const int g = lane >> 2, t = lane & 3;

    const int q0 = blockIdx.x * 128;
    const int h = blockIdx.y;
    const int hoff = h * DK;
    const size_t vbase = (size_t)h * DK * L_SEQ;

    // Load Q tile (128 x 64)
    {
        const __nv_bfloat16* qh = Qh_g + (size_t)q0 * DM + hoff;
        const __nv_bfloat16* ql = Ql_g + (size_t)q0 * DM + hoff;
#pragma unroll
        for (int p = 0; p < 4; p++) {
            int f = tid + p * 256;
            int r = f >> 3;
            int c8 = (f & 7) * 8;
            *(uint4*)&Qsh[r * PIT + c8] = *(const uint4*)&qh[(size_t)r * DM + c8];
            *(uint4*)&Qsl[r * PIT + c8] = *(const uint4*)&ql[(size_t)r * DM + c8];
        }
    }

    float o[8][4];
#pragma unroll
    for (int ni = 0; ni < 8; ni++)
#pragma unroll
        for (int j = 0; j < 4; j++) o[ni][j] = 0.f;
    float m0 = -1e30f, m1 = -1e30f, l0 = 0.f, l1 = 0.f;

    for (int kt = 0; kt < L_SEQ / 64; kt++) {
        const int k0 = kt * 64;
        __syncthreads();
        // Load K (64x64) and Vt (64d x 64key)
        {
            const __nv_bfloat16* kh = Kh_g + (size_t)k0 * DM + hoff;
            const __nv_bfloat16* kl = Kl_g + (size_t)k0 * DM + hoff;
            const __nv_bfloat16* vh = Vh_g + vbase + k0;
            const __nv_bfloat16* vl = Vl_g + vbase + k0;
#pragma unroll
            for (int p = 0; p < 2; p++) {
                int f = tid + p * 256;
                int r = f >> 3;
                int c8 = (f & 7) * 8;
                *(uint4*)&Ksh[r * PIT + c8] = *(const uint4*)&kh[(size_t)r * DM + c8];
                *(uint4*)&Ksl[r * PIT + c8] = *(const uint4*)&kl[(size_t)r * DM + c8];
                *(uint4*)&Vsh[r * PIT + c8] = *(const uint4*)&vh[(size_t)r * L_SEQ + c8];
                *(uint4*)&Vsl[r * PIT + c8] = *(const uint4*)&vl[(size_t)r * L_SEQ + c8];
            }
        }
        __syncthreads();

        // S = Q K^T   (16 x 64 per warp)
        float s[8][4];
#pragma unroll
        for (int ni = 0; ni < 8; ni++)
#pragma unroll
            for (int j = 0; j < 4; j++) s[ni][j] = 0.f;

#pragma unroll
        for (int kk = 0; kk < 4; kk++) {
            const int kc = kk * 16;
            u32 ah[4], al[4];
            const __nv_bfloat16* pH = &Qsh[(mb + g) * PIT + kc + 2 * t];
            const __nv_bfloat16* pL = &Qsl[(mb + g) * PIT + kc + 2 * t];
            ah[0] = *(const u32*)pH;           ah[1] = *(const u32*)(pH + 8 * PIT);
            ah[2] = *(const u32*)(pH + 8);     ah[3] = *(const u32*)(pH + 8 * PIT + 8);
            al[0] = *(const u32*)pL;           al[1] = *(const u32*)(pL + 8 * PIT);
            al[2] = *(const u32*)(pL + 8);     al[3] = *(const u32*)(pL + 8 * PIT + 8);
#pragma unroll
            for (int ni = 0; ni < 8; ni++) {
                const __nv_bfloat16* bH = &Ksh[(ni * 8 + g) * PIT + kc + 2 * t];
                const __nv_bfloat16* bL = &Ksl[(ni * 8 + g) * PIT + kc + 2 * t];
                u32 bh[2] = { *(const u32*)bH, *(const u32*)(bH + 8) };
                u32 bl[2] = { *(const u32*)bL, *(const u32*)(bL + 8) };
                MMA_BF16(s[ni], ah, bh);
                MMA_BF16(s[ni], ah, bl);
                MMA_BF16(s[ni], al, bh);
            }
        }

        // Online softmax (rows mb+g and mb+8+g), scale 1/sqrt(64)=0.125
        float rmax0 = -1e30f, rmax1 = -1e30f;
#pragma unroll
        for (int ni = 0; ni < 8; ni++) {
            s[ni][0] *= 0.125f; s[ni][1] *= 0.125f;
            s[ni][2] *= 0.125f; s[ni][3] *= 0.125f;
            rmax0 = fmaxf(rmax0, fmaxf(s[ni][0], s[ni][1]));
            rmax1 = fmaxf(rmax1, fmaxf(s[ni][2], s[ni][3]));
        }
        rmax0 = fmaxf(rmax0, __shfl_xor_sync(0xffffffffu, rmax0, 1));
        rmax0 = fmaxf(rmax0, __shfl_xor_sync(0xffffffffu, rmax0, 2));
        rmax1 = fmaxf(rmax1, __shfl_xor_sync(0xffffffffu, rmax1, 1));
        rmax1 = fmaxf(rmax1, __shfl_xor_sync(0xffffffffu, rmax1, 2));
        float mn0 = fmaxf(m0, rmax0), mn1 = fmaxf(m1, rmax1);
        float corr0 = __expf(m0 - mn0), corr1 = __expf(m1 - mn1);
        float rs0 = 0.f, rs1 = 0.f;
#pragma unroll
        for (int ni = 0; ni < 8; ni++) {
            float p0 = __expf(s[ni][0] - mn0);
            float p1 = __expf(s[ni][1] - mn0);
            float p2 = __expf(s[ni][2] - mn1);
            float p3 = __expf(s[ni][3] - mn1);
            rs0 += p0 + p1;
            rs1 += p2 + p3;
            HL x = split2(p0, p1);
            *(u32*)&Psh[(mb + g) * PIT + ni * 8 + 2 * t] = x.h;
            *(u32*)&Psl[(mb + g) * PIT + ni * 8 + 2 * t] = x.l;
            HL y = split2(p2, p3);
            *(u32*)&Psh[(mb + 8 + g) * PIT + ni * 8 + 2 * t] = y.h;
            *(u32*)&Psl[(mb + 8 + g) * PIT + ni * 8 + 2 * t] = y.l;
        }
        rs0 += __shfl_xor_sync(0xffffffffu, rs0, 1);
        rs0 += __shfl_xor_sync(0xffffffffu, rs0, 2);
        rs1 += __shfl_xor_sync(0xffffffffu, rs1, 1);
        rs1 += __shfl_xor_sync(0xffffffffu, rs1, 2);
        l0 = l0 * corr0 + rs0;
        l1 = l1 * corr1 + rs1;
        m0 = mn0; m1 = mn1;
#pragma unroll
        for (int ni = 0; ni < 8; ni++) {
            o[ni][0] *= corr0; o[ni][1] *= corr0;
            o[ni][2] *= corr1; o[ni][3] *= corr1;
        }
        __syncthreads();

        // O += P V    (16 x 64 per warp, k over 64 keys)
#pragma unroll
        for (int kk = 0; kk < 4; kk++) {
            const int kc = kk * 16;
            u32 ph[4], pl[4];
            const __nv_bfloat16* pH = &Psh[(mb + g) * PIT + kc + 2 * t];
            const __nv_bfloat16* pL = &Psl[(mb + g) * PIT + kc + 2 * t];
            ph[0] = *(const u32*)pH;           ph[1] = *(const u32*)(pH + 8 * PIT);
            ph[2] = *(const u32*)(pH + 8);     ph[3] = *(const u32*)(pH + 8 * PIT + 8);
            pl[0] = *(const u32*)pL;           pl[1] = *(const u32*)(pL + 8 * PIT);
            pl[2] = *(const u32*)(pL + 8);     pl[3] = *(const u32*)(pL + 8 * PIT + 8);
#pragma unroll
            for (int ni = 0; ni < 8; ni++) {
                const __nv_bfloat16* bH = &Vsh[(ni * 8 + g) * PIT + kc + 2 * t];
                const __nv_bfloat16* bL = &Vsl[(ni * 8 + g) * PIT + kc + 2 * t];
                u32 vh[2] = { *(const u32*)bH, *(const u32*)(bH + 8) };
                u32 vl[2] = { *(const u32*)bL, *(const u32*)(bL + 8) };
                MMA_BF16(o[ni], ph, vh);
                MMA_BF16(o[ni], ph, vl);
                MMA_BF16(o[ni], pl, vh);
            }
        }
    }

    // Epilogue: normalize + split-write att
    float inv0 = 1.f / l0, inv1 = 1.f / l1;
#pragma unroll
    for (int ni = 0; ni < 8; ni++) {
        int row = q0 + mb + g;
        int col = hoff + ni * 8 + 2 * t;
        HL x = split2(o[ni][0] * inv0, o[ni][1] * inv0);
        *(u32*)&Oh_g[(size_t)row * DM + col] = x.h;
        *(u32*)&Ol_g[(size_t)row * DM + col] = x.l;
        HL y = split2(o[ni][2] * inv1, o[ni][3] * inv1);
        *(u32*)&Oh_g[(size_t)(row + 8) * DM + col] = y.h;
        *(u32*)&Ol_g[(size_t)(row + 8) * DM + col] = y.l;
    }
}

// ---------------------------------------------------------------------------
extern "C" void kernel_launch(void* const* d_in, const int* in_sizes, int n_in,
                              void* d_out, int out_size)
{
    const float* q  = (const float*)d_in[0];
    const float* k  = (const float*)d_in[1];
    const float* v  = (const float*)d_in[2];
    const float* Wq = (const float*)d_in[3];
    const float* bq = (const float*)d_in[4];
    const float* Wk = (const float*)d_in[5];
    const float* bk = (const float*)d_in[6];
    const float* Wv = (const float*)d_in[7];
    const float* bv = (const float*)d_in[8];
    const float* Wo = (const float*)d_in[9];
    const float* bo = (const float*)d_in[10];
    float* out = (float*)d_out;

    __nv_bfloat16 *inq_h, *inq_l, *ink_h, *ink_l, *inv_h, *inv_l;
    __nv_bfloat16 *wq_h, *wq_l, *wk_h, *wk_l, *wv_h, *wv_l, *wo_h, *wo_l;
    __nv_bfloat16 *qp_h, *qp_l, *kp_h, *kp_l, *vt_h, *vt_l, *att_h, *att_l;
    cudaGetSymbolAddress((void**)&inq_h, g_inq_h); cudaGetSymbolAddress((void**)&inq_l, g_inq_l);
    cudaGetSymbolAddress((void**)&ink_h, g_ink_h); cudaGetSymbolAddress((void**)&ink_l, g_ink_l);
    cudaGetSymbolAddress((void**)&inv_h, g_inv_h); cudaGetSymbolAddress((void**)&inv_l, g_inv_l);
    cudaGetSymbolAddress((void**)&wq_h, g_wq_h);   cudaGetSymbolAddress((void**)&wq_l, g_wq_l);
    cudaGetSymbolAddress((void**)&wk_h, g_wk_h);   cudaGetSymbolAddress((void**)&wk_l, g_wk_l);
    cudaGetSymbolAddress((void**)&wv_h, g_wv_h);   cudaGetSymbolAddress((void**)&wv_l, g_wv_l);
    cudaGetSymbolAddress((void**)&wo_h, g_wo_h);   cudaGetSymbolAddress((void**)&wo_l, g_wo_l);
    cudaGetSymbolAddress((void**)&qp_h, g_qp_h);   cudaGetSymbolAddress((void**)&qp_l, g_qp_l);
    cudaGetSymbolAddress((void**)&kp_h, g_kp_h);   cudaGetSymbolAddress((void**)&kp_l, g_kp_l);
    cudaGetSymbolAddress((void**)&vt_h, g_vt_h);   cudaGetSymbolAddress((void**)&vt_l, g_vt_l);
    cudaGetSymbolAddress((void**)&att_h, g_att_h); cudaGetSymbolAddress((void**)&att_l, g_att_l);

    static bool attr_set = false;
    if (!attr_set) {
        cudaFuncSetAttribute(flash_mma_kernel,
                             cudaFuncAttributeMaxDynamicSharedMemorySize,
                             FLASH_SMEM_BYTES);
        attr_set = true;
    }

    const int nAct = L_SEQ * DM;   // 3,145,728
    const int nW = DM * DM;        // 589,824

    // 1) split inputs + weights to bf16 hi/lo
    convert_split_kernel<<<nAct / 1024, 256>>>(q, inq_h, inq_l, nAct);
    convert_split_kernel<<<nAct / 1024, 256>>>(k, ink_h, ink_l, nAct);
    convert_split_kernel<<<nAct / 1024, 256>>>(v, inv_h, inv_l, nAct);
    convert_split_kernel<<<nW / 1024, 256>>>(Wq, wq_h, wq_l, nW);
    convert_split_kernel<<<nW / 1024, 256>>>(Wk, wk_h, wk_l, nW);
    convert_split_kernel<<<nW / 1024, 256>>>(Wv, wv_h, wv_l, nW);
    convert_split_kernel<<<nW / 1024, 256>>>(Wo, wo_h, wo_l, nW);

    dim3 ggrid(DM / 128, L_SEQ / 128);   // (6, 32)

    // 2) projections (bf16 hi/lo outputs; V transposed per-head)
    gemm_mma_kernel<1><<<ggrid, 256>>>(inq_h, inq_l, wq_h, wq_l, bq, nullptr, qp_h, qp_l);
    gemm_mma_kernel<1><<<ggrid, 256>>>(ink_h, ink_l, wk_h, wk_l, bk, nullptr, kp_h, kp_l);
    gemm_mma_kernel<2><<<ggrid, 256>>>(inv_h, inv_l, wv_h, wv_l, bv, nullptr, vt_h, vt_l);

    // 3) attention
    dim3 fgrid(L_SEQ / 128, NH);
    flash_mma_kernel<<<fgrid, 256, FLASH_SMEM_BYTES>>>(
        qp_h, qp_l, kp_h, kp_l, vt_h, vt_l, att_h, att_l);

    // 4) output projection (fp32 out)
    gemm_mma_kernel<0><<<ggrid, 256>>>(att_h, att_l, wo_h, wo_l, bo, out, nullptr, nullptr);
}

// round 4
// speedup vs baseline: 2.4305x; 1.0029x over previous
#include <cuda_runtime.h>
#include <cuda_bf16.h>

#define L_SEQ 4096
#define DM 768
#define NH 12
#define DK 64

typedef unsigned int u32;

// ---------------------------------------------------------------------------
// Device scratch (bf16 hi/lo split arrays)
// ---------------------------------------------------------------------------
__device__ __nv_bfloat16 g_inq_h[L_SEQ * DM], g_inq_l[L_SEQ * DM];
__device__ __nv_bfloat16 g_ink_h[L_SEQ * DM], g_ink_l[L_SEQ * DM];
__device__ __nv_bfloat16 g_inv_h[L_SEQ * DM], g_inv_l[L_SEQ * DM];
__device__ __nv_bfloat16 g_wq_h[DM * DM], g_wq_l[DM * DM];
__device__ __nv_bfloat16 g_wk_h[DM * DM], g_wk_l[DM * DM];
__device__ __nv_bfloat16 g_wv_h[DM * DM], g_wv_l[DM * DM];
__device__ __nv_bfloat16 g_wo_h[DM * DM], g_wo_l[DM * DM];
__device__ __nv_bfloat16 g_qp_h[L_SEQ * DM], g_qp_l[L_SEQ * DM];
__device__ __nv_bfloat16 g_kp_h[L_SEQ * DM], g_kp_l[L_SEQ * DM];
__device__ __nv_bfloat16 g_vt_h[L_SEQ * DM], g_vt_l[L_SEQ * DM];   // [h][d][key]
__device__ __nv_bfloat16 g_att_h[L_SEQ * DM], g_att_l[L_SEQ * DM];

// ---------------------------------------------------------------------------
// Helpers
// ---------------------------------------------------------------------------
struct HL { u32 h, l; };

// split pair (x -> low half / even col, y -> high half / odd col)
__device__ __forceinline__ HL split2(float x, float y) {
    __nv_bfloat162 hb = __floats2bfloat162_rn(x, y);
    float2 hf = __bfloat1622float2(hb);
    __nv_bfloat162 lb = __floats2bfloat162_rn(x - hf.x, y - hf.y);
    HL r;
    r.h = *reinterpret_cast<u32*>(&hb);
    r.l = *reinterpret_cast<u32*>(&lb);
    return r;
}

__device__ __forceinline__ void split1(float v, __nv_bfloat16* ph, __nv_bfloat16* pl) {
    __nv_bfloat16 hb = __float2bfloat16_rn(v);
    *ph = hb;
    *pl = __float2bfloat16_rn(v - __bfloat162float(hb));
}

#define MMA_BF16(D, A, B) asm volatile( \
    "mma.sync.aligned.m16n8k16.row.col.f32.bf16.bf16.f32 " \
    "{%0,%1,%2,%3},{%4,%5,%6,%7},{%8,%9},{%0,%1,%2,%3};\n" \
    : "+f"((D)[0]), "+f"((D)[1]), "+f"((D)[2]), "+f"((D)[3]) \
    : "r"((A)[0]), "r"((A)[1]), "r"((A)[2]), "r"((A)[3]), \
      "r"((B)[0]), "r"((B)[1]))

// ---------------------------------------------------------------------------
// fp32 -> bf16 hi/lo split (elementwise)
// ---------------------------------------------------------------------------
__global__ void convert_split_kernel(const float* __restrict__ src,
                                     __nv_bfloat16* __restrict__ dh,
                                     __nv_bfloat16* __restrict__ dl, int n)
{
    int i = (blockIdx.x * blockDim.x + threadIdx.x) * 4;
    if (i >= n) return;
    float4 x = *(const float4*)(src + i);
    HL a = split2(x.x, x.y);
    HL b = split2(x.z, x.w);
    *(uint2*)(dh + i) = make_uint2(a.h, b.h);
    *(uint2*)(dl + i) = make_uint2(a.l, b.l);
}

// ---------------------------------------------------------------------------
// GEMM: C[M,768] = A[M,768] @ W^T + b, bf16-split 3-pass MMA, fp32 accum.
// BM=128, BN=128, BK=32, 256 thr (8 warps, 4x2), warp tile 32x64.
// MODE 0: fp32 out.  MODE 1: bf16 hi/lo out.  MODE 2: bf16 hi/lo, per-head
// transposed out [h][d][m] (for V).
// ---------------------------------------------------------------------------
template <int MODE>
__global__ __launch_bounds__(256, 2) void gemm_mma_kernel(
    const __nv_bfloat16* __restrict__ Ah, const __nv_bfloat16* __restrict__ Al,
    const __nv_bfloat16* __restrict__ Wh, const __nv_bfloat16* __restrict__ Wl,
    const float* __restrict__ bias,
    float* __restrict__ Cf,
    __nv_bfloat16* __restrict__ Ch, __nv_bfloat16* __restrict__ Cl)
{
    __shared__ __nv_bfloat16 AsH[128 * 40], AsL[128 * 40];
    __shared__ __nv_bfloat16 WsH[128 * 40], WsL[128 * 40];

    const int tid = threadIdx.x;
    const int lane = tid & 31;
    const int w = tid >> 5;
    const int wm = w >> 1, wn = w & 1;
    const int mb0 = wm * 32;
    const int nb0 = wn * 64;
    const int g = lane >> 2, t = lane & 3;

    const int m0 = blockIdx.y * 128;
    const int n0 = blockIdx.x * 128;

    float acc[2][8][4];
#pragma unroll
    for (int mi = 0; mi < 2; mi++)
#pragma unroll
        for (int ni = 0; ni < 8; ni++)
#pragma unroll
            for (int j = 0; j < 4; j++) acc[mi][ni][j] = 0.f;

    for (int kt = 0; kt < DM / 32; kt++) {
        __syncthreads();
        const __nv_bfloat16* aH = Ah + (size_t)m0 * DM + kt * 32;
        const __nv_bfloat16* aL = Al + (size_t)m0 * DM + kt * 32;
        const __nv_bfloat16* wH = Wh + (size_t)n0 * DM + kt * 32;
        const __nv_bfloat16* wL = Wl + (size_t)n0 * DM + kt * 32;
#pragma unroll
        for (int p = 0; p < 2; p++) {
            int f = tid + p * 256;
            int r = f >> 2;
            int c8 = (f & 3) * 8;
            *(uint4*)&AsH[r * 40 + c8] = *(const uint4*)&aH[(size_t)r * DM + c8];
            *(uint4*)&AsL[r * 40 + c8] = *(const uint4*)&aL[(size_t)r * DM + c8];
            *(uint4*)&WsH[r * 40 + c8] = *(const uint4*)&wH[(size_t)r * DM + c8];
            *(uint4*)&WsL[r * 40 + c8] = *(const uint4*)&wL[(size_t)r * DM + c8];
        }
        __syncthreads();

#pragma unroll
        for (int kk = 0; kk < 2; kk++) {
            const int k0 = kk * 16;
            u32 ah[2][4], al[2][4];
#pragma unroll
            for (int mi = 0; mi < 2; mi++) {
                const __nv_bfloat16* pH = &AsH[(mb0 + mi * 16 + g) * 40 + k0 + 2 * t];
                const __nv_bfloat16* pL = &AsL[(mb0 + mi * 16 + g) * 40 + k0 + 2 * t];
                ah[mi][0] = *(const u32*)pH;
                ah[mi][1] = *(const u32*)(pH + 8 * 40);
                ah[mi][2] = *(const u32*)(pH + 8);
                ah[mi][3] = *(const u32*)(pH + 8 * 40 + 8);
                al[mi][0] = *(const u32*)pL;
                al[mi][1] = *(const u32*)(pL + 8 * 40);
                al[mi][2] = *(const u32*)(pL + 8);
                al[mi][3] = *(const u32*)(pL + 8 * 40 + 8);
            }
#pragma unroll
            for (int ni = 0; ni < 8; ni++) {
                const __nv_bfloat16* bH = &WsH[(nb0 + ni * 8 + g) * 40 + k0 + 2 * t];
                const __nv_bfloat16* bL = &WsL[(nb0 + ni * 8 + g) * 40 + k0 + 2 * t];
                u32 bh[2] = { *(const u32*)bH, *(const u32*)(bH + 8) };
                u32 bl[2] = { *(const u32*)bL, *(const u32*)(bL + 8) };
#pragma unroll
                for (int mi = 0; mi < 2; mi++) {
                    MMA_BF16(acc[mi][ni], ah[mi], bh);
                    MMA_BF16(acc[mi][ni], ah[mi], bl);
                    MMA_BF16(acc[mi][ni], al[mi], bh);
                }
            }
        }
    }

    // Epilogue
#pragma unroll
    for (int mi = 0; mi < 2; mi++) {
#pragma unroll
        for (int ni = 0; ni < 8; ni++) {
            int mg = m0 + mb0 + mi * 16 + g;
            int ng = n0 + nb0 + ni * 8 + 2 * t;
            float b0 = bias[ng], b1 = bias[ng + 1];
            float c0 = acc[mi][ni][0] + b0, c1 = acc[mi][ni][1] + b1;
            float c2 = acc[mi][ni][2] + b0, c3 = acc[mi][ni][3] + b1;
            if (MODE == 0) {
                *(float2*)&Cf[(size_t)mg * DM + ng] = make_float2(c0, c1);
                *(float2*)&Cf[(size_t)(mg + 8) * DM + ng] = make_float2(c2, c3);
            } else if (MODE == 1) {
                HL x = split2(c0, c1);
                *(u32*)&Ch[(size_t)mg * DM + ng] = x.h;
                *(u32*)&Cl[(size_t)mg * DM + ng] = x.l;
                HL y = split2(c2, c3);
                *(u32*)&Ch[(size_t)(mg + 8) * DM + ng] = y.h;
                *(u32*)&Cl[(size_t)(mg + 8) * DM + ng] = y.l;
            } else {
                int hh = ng >> 6, dd = ng & 63;
                size_t base = (size_t)hh * (DK * L_SEQ) + (size_t)dd * L_SEQ;
                split1(c0, &Ch[base + mg], &Cl[base + mg]);
                split1(c1, &Ch[base + L_SEQ + mg], &Cl[base + L_SEQ + mg]);
                split1(c2, &Ch[base + mg + 8], &Cl[base + mg + 8]);
                split1(c3, &Ch[base + L_SEQ + mg + 8], &Cl[base + L_SEQ + mg + 8]);
            }
        }
    }
}

// ---------------------------------------------------------------------------
// Flash attention, bf16-split 3-pass MMA. Br=128 q rows, Bc=64 keys,
// 8 warps: warp w owns query rows 16w..16w+15.
// ---------------------------------------------------------------------------
#define PIT 72
#define OFF_QH 0
#define OFF_QL (128 * PIT)
#define OFF_KH (2 * 128 * PIT)
#define OFF_KL (2 * 128 * PIT + 64 * PIT)
#define OFF_VH (2 * 128 * PIT + 2 * 64 * PIT)
#define OFF_VL (2 * 128 * PIT + 3 * 64 * PIT)
#define OFF_PH (2 * 128 * PIT + 4 * 64 * PIT)
#define OFF_PL (3 * 128 * PIT + 4 * 64 * PIT)
#define FLASH_SMEM_ELEMS (4 * 128 * PIT + 4 * 64 * PIT)
#define FLASH_SMEM_BYTES (FLASH_SMEM_ELEMS * 2)

__global__ __launch_bounds__(256, 2) void flash_mma_kernel(
    const __nv_bfloat16* __restrict__ Qh_g, const __nv_bfloat16* __restrict__ Ql_g,
    const __nv_bfloat16* __restrict__ Kh_g, const __nv_bfloat16* __restrict__ Kl_g,
    const __nv_bfloat16* __restrict__ Vh_g, const __nv_bfloat16* __restrict__ Vl_g,
    __nv_bfloat16* __restrict__ Oh_g, __nv_bfloat16* __restrict__ Ol_g)
{
    extern __shared__ __nv_bfloat16 sm[];
    __nv_bfloat16* Qsh = sm + OFF_QH;
    __nv_bfloat16* Qsl = sm + OFF_QL;
    __nv_bfloat16* Ksh = sm + OFF_KH;
    __nv_bfloat16* Ksl = sm + OFF_KL;
    __nv_bfloat16* Vsh = sm + OFF_VH;
    __nv_bfloat16* Vsl = sm + OFF_VL;
    __nv_bfloat16* Psh = sm + OFF_PH;
    __nv_bfloat16* Psl = sm + OFF_PL;

    const int tid = threadIdx.x;
    const int lane = tid & 31;
    const int w = tid >> 5;
    const int mb = w * 16;
    const int g = lane >> 2, t = lane & 3;

    const int q0 = blockIdx.x * 128;
    const int h = blockIdx.y;
    const int hoff = h * DK;
    const size_t vbase = (size_t)h * DK * L_SEQ;

    // Load Q tile (128 x 64)
    {
        const __nv_bfloat16* qh = Qh_g + (size_t)q0 * DM + hoff;
        const __nv_bfloat16* ql = Ql_g + (size_t)q0 * DM + hoff;
#pragma unroll
        for (int p = 0; p < 4; p++) {
            int f = tid + p * 256;
            int r = f >> 3;
            int c8 = (f & 7) * 8;
            *(uint4*)&Qsh[r * PIT + c8] = *(const uint4*)&qh[(size_t)r * DM + c8];
            *(uint4*)&Qsl[r * PIT + c8] = *(const uint4*)&ql[(size_t)r * DM + c8];
        }
    }

    float o[8][4];
#pragma unroll
    for (int ni = 0; ni < 8; ni++)
#pragma unroll
        for (int j = 0; j < 4; j++) o[ni][j] = 0.f;
    float m0 = -1e30f, m1 = -1e30f, l0 = 0.f, l1 = 0.f;

    for (int kt = 0; kt < L_SEQ / 64; kt++) {
        const int k0 = kt * 64;
        __syncthreads();
        // Load K (64x64) and Vt (64d x 64key)
        {
            const __nv_bfloat16* kh = Kh_g + (size_t)k0 * DM + hoff;
            const __nv_bfloat16* kl = Kl_g + (size_t)k0 * DM + hoff;
            const __nv_bfloat16* vh = Vh_g + vbase + k0;
            const __nv_bfloat16* vl = Vl_g + vbase + k0;
#pragma unroll
            for (int p = 0; p < 2; p++) {
                int f = tid + p * 256;
                int r = f >> 3;
                int c8 = (f & 7) * 8;
                *(uint4*)&Ksh[r * PIT + c8] = *(const uint4*)&kh[(size_t)r * DM + c8];
                *(uint4*)&Ksl[r * PIT + c8] = *(const uint4*)&kl[(size_t)r * DM + c8];
                *(uint4*)&Vsh[r * PIT + c8] = *(const uint4*)&vh[(size_t)r * L_SEQ + c8];
                *(uint4*)&Vsl[r * PIT + c8] = *(const uint4*)&vl[(size_t)r * L_SEQ + c8];
            }
        }
        __syncthreads();

        // S = Q K^T   (16 x 64 per warp)
        float s[8][4];
#pragma unroll
        for (int ni = 0; ni < 8; ni++)
#pragma unroll
            for (int j = 0; j < 4; j++) s[ni][j] = 0.f;

#pragma unroll
        for (int kk = 0; kk < 4; kk++) {
            const int kc = kk * 16;
            u32 ah[4], al[4];
            const __nv_bfloat16* pH = &Qsh[(mb + g) * PIT + kc + 2 * t];
            const __nv_bfloat16* pL = &Qsl[(mb + g) * PIT + kc + 2 * t];
            ah[0] = *(const u32*)pH;           ah[1] = *(const u32*)(pH + 8 * PIT);
            ah[2] = *(const u32*)(pH + 8);     ah[3] = *(const u32*)(pH + 8 * PIT + 8);
            al[0] = *(const u32*)pL;           al[1] = *(const u32*)(pL + 8 * PIT);
            al[2] = *(const u32*)(pL + 8);     al[3] = *(const u32*)(pL + 8 * PIT + 8);
#pragma unroll
            for (int ni = 0; ni < 8; ni++) {
                const __nv_bfloat16* bH = &Ksh[(ni * 8 + g) * PIT + kc + 2 * t];
                const __nv_bfloat16* bL = &Ksl[(ni * 8 + g) * PIT + kc + 2 * t];
                u32 bh[2] = { *(const u32*)bH, *(const u32*)(bH + 8) };
                u32 bl[2] = { *(const u32*)bL, *(const u32*)(bL + 8) };
                MMA_BF16(s[ni], ah, bh);
                MMA_BF16(s[ni], ah, bl);
                MMA_BF16(s[ni], al, bh);
            }
        }

        // Online softmax (rows mb+g and mb+8+g), scale 1/sqrt(64)=0.125
        float rmax0 = -1e30f, rmax1 = -1e30f;
#pragma unroll
        for (int ni = 0; ni < 8; ni++) {
            s[ni][0] *= 0.125f; s[ni][1] *= 0.125f;
            s[ni][2] *= 0.125f; s[ni][3] *= 0.125f;
            rmax0 = fmaxf(rmax0, fmaxf(s[ni][0], s[ni][1]));
            rmax1 = fmaxf(rmax1, fmaxf(s[ni][2], s[ni][3]));
        }
        rmax0 = fmaxf(rmax0, __shfl_xor_sync(0xffffffffu, rmax0, 1));
        rmax0 = fmaxf(rmax0, __shfl_xor_sync(0xffffffffu, rmax0, 2));
        rmax1 = fmaxf(rmax1, __shfl_xor_sync(0xffffffffu, rmax1, 1));
        rmax1 = fmaxf(rmax1, __shfl_xor_sync(0xffffffffu, rmax1, 2));
        float mn0 = fmaxf(m0, rmax0), mn1 = fmaxf(m1, rmax1);
        float corr0 = __expf(m0 - mn0), corr1 = __expf(m1 - mn1);
        float rs0 = 0.f, rs1 = 0.f;
#pragma unroll
        for (int ni = 0; ni < 8; ni++) {
            float p0 = __expf(s[ni][0] - mn0);
            float p1 = __expf(s[ni][1] - mn0);
            float p2 = __expf(s[ni][2] - mn1);
            float p3 = __expf(s[ni][3] - mn1);
            rs0 += p0 + p1;
            rs1 += p2 + p3;
            HL x = split2(p0, p1);
            *(u32*)&Psh[(mb + g) * PIT + ni * 8 + 2 * t] = x.h;
            *(u32*)&Psl[(mb + g) * PIT + ni * 8 + 2 * t] = x.l;
            HL y = split2(p2, p3);
            *(u32*)&Psh[(mb + 8 + g) * PIT + ni * 8 + 2 * t] = y.h;
            *(u32*)&Psl[(mb + 8 + g) * PIT + ni * 8 + 2 * t] = y.l;
        }
        rs0 += __shfl_xor_sync(0xffffffffu, rs0, 1);
        rs0 += __shfl_xor_sync(0xffffffffu, rs0, 2);
        rs1 += __shfl_xor_sync(0xffffffffu, rs1, 1);
        rs1 += __shfl_xor_sync(0xffffffffu, rs1, 2);
        l0 = l0 * corr0 + rs0;
        l1 = l1 * corr1 + rs1;
        m0 = mn0; m1 = mn1;
#pragma unroll
        for (int ni = 0; ni < 8; ni++) {
            o[ni][0] *= corr0; o[ni][1] *= corr0;
            o[ni][2] *= corr1; o[ni][3] *= corr1;
        }
        __syncthreads();

        // O += P V    (16 x 64 per warp, k over 64 keys)
#pragma unroll
        for (int kk = 0; kk < 4; kk++) {
            const int kc = kk * 16;
            u32 ph[4], pl[4];
            const __nv_bfloat16* pH = &Psh[(mb + g) * PIT + kc + 2 * t];
            const __nv_bfloat16* pL = &Psl[(mb + g) * PIT + kc + 2 * t];
            ph[0] = *(const u32*)pH;           ph[1] = *(const u32*)(pH + 8 * PIT);
            ph[2] = *(const u32*)(pH + 8);     ph[3] = *(const u32*)(pH + 8 * PIT + 8);
            pl[0] = *(const u32*)pL;           pl[1] = *(const u32*)(pL + 8 * PIT);
            pl[2] = *(const u32*)(pL + 8);     pl[3] = *(const u32*)(pL + 8 * PIT + 8);
#pragma unroll
            for (int ni = 0; ni < 8; ni++) {
                const __nv_bfloat16* bH = &Vsh[(ni * 8 + g) * PIT + kc + 2 * t];
                const __nv_bfloat16* bL = &Vsl[(ni * 8 + g) * PIT + kc + 2 * t];
                u32 vh[2] = { *(const u32*)bH, *(const u32*)(bH + 8) };
                u32 vl[2] = { *(const u32*)bL, *(const u32*)(bL + 8) };
                MMA_BF16(o[ni], ph, vh);
                MMA_BF16(o[ni], ph, vl);
                MMA_BF16(o[ni], pl, vh);
            }
        }
    }

    // Epilogue: normalize + split-write att
    float inv0 = 1.f / l0, inv1 = 1.f / l1;
#pragma unroll
    for (int ni = 0; ni < 8; ni++) {
        int row = q0 + mb + g;
        int col = hoff + ni * 8 + 2 * t;
        HL x = split2(o[ni][0] * inv0, o[ni][1] * inv0);
        *(u32*)&Oh_g[(size_t)row * DM + col] = x.h;
        *(u32*)&Ol_g[(size_t)row * DM + col] = x.l;
        HL y = split2(o[ni][2] * inv1, o[ni][3] * inv1);
        *(u32*)&Oh_g[(size_t)(row + 8) * DM + col] = y.h;
        *(u32*)&Ol_g[(size_t)(row + 8) * DM + col] = y.l;
    }
}

// ---------------------------------------------------------------------------
extern "C" void kernel_launch(void* const* d_in, const int* in_sizes, int n_in,
                              void* d_out, int out_size)
{
    const float* q  = (const float*)d_in[0];
    const float* k  = (const float*)d_in[1];
    const float* v  = (const float*)d_in[2];
    const float* Wq = (const float*)d_in[3];
    const float* bq = (const float*)d_in[4];
    const float* Wk = (const float*)d_in[5];
    const float* bk = (const float*)d_in[6];
    const float* Wv = (const float*)d_in[7];
    const float* bv = (const float*)d_in[8];
    const float* Wo = (const float*)d_in[9];
    const float* bo = (const float*)d_in[10];
    float* out = (float*)d_out;

    __nv_bfloat16 *inq_h, *inq_l, *ink_h, *ink_l, *inv_h, *inv_l;
    __nv_bfloat16 *wq_h, *wq_l, *wk_h, *wk_l, *wv_h, *wv_l, *wo_h, *wo_l;
    __nv_bfloat16 *qp_h, *qp_l, *kp_h, *kp_l, *vt_h, *vt_l, *att_h, *att_l;
    cudaGetSymbolAddress((void**)&inq_h, g_inq_h); cudaGetSymbolAddress((void**)&inq_l, g_inq_l);
    cudaGetSymbolAddress((void**)&ink_h, g_ink_h); cudaGetSymbolAddress((void**)&ink_l, g_ink_l);
    cudaGetSymbolAddress((void**)&inv_h, g_inv_h); cudaGetSymbolAddress((void**)&inv_l, g_inv_l);
    cudaGetSymbolAddress((void**)&wq_h, g_wq_h);   cudaGetSymbolAddress((void**)&wq_l, g_wq_l);
    cudaGetSymbolAddress((void**)&wk_h, g_wk_h);   cudaGetSymbolAddress((void**)&wk_l, g_wk_l);
    cudaGetSymbolAddress((void**)&wv_h, g_wv_h);   cudaGetSymbolAddress((void**)&wv_l, g_wv_l);
    cudaGetSymbolAddress((void**)&wo_h, g_wo_h);   cudaGetSymbolAddress((void**)&wo_l, g_wo_l);
    cudaGetSymbolAddress((void**)&qp_h, g_qp_h);   cudaGetSymbolAddress((void**)&qp_l, g_qp_l);
    cudaGetSymbolAddress((void**)&kp_h, g_kp_h);   cudaGetSymbolAddress((void**)&kp_l, g_kp_l);
    cudaGetSymbolAddress((void**)&vt_h, g_vt_h);   cudaGetSymbolAddress((void**)&vt_l, g_vt_l);
    cudaGetSymbolAddress((void**)&att_h, g_att_h); cudaGetSymbolAddress((void**)&att_l, g_att_l);

    static bool attr_set = false;
    if (!attr_set) {
        cudaFuncSetAttribute(flash_mma_kernel,
                             cudaFuncAttributeMaxDynamicSharedMemorySize,
                             FLASH_SMEM_BYTES);
        attr_set = true;
    }

    const int nAct = L_SEQ * DM;   // 3,145,728
    const int nW = DM * DM;        // 589,824

    // 1) split inputs + weights to bf16 hi/lo
    convert_split_kernel<<<nAct / 1024, 256>>>(q, inq_h, inq_l, nAct);
    convert_split_kernel<<<nAct / 1024, 256>>>(k, ink_h, ink_l, nAct);
    convert_split_kernel<<<nAct / 1024, 256>>>(v, inv_h, inv_l, nAct);
    convert_split_kernel<<<nW / 1024, 256>>>(Wq, wq_h, wq_l, nW);
    convert_split_kernel<<<nW / 1024, 256>>>(Wk, wk_h, wk_l, nW);
    convert_split_kernel<<<nW / 1024, 256>>>(Wv, wv_h, wv_l, nW);
    convert_split_kernel<<<nW / 1024, 256>>>(Wo, wo_h, wo_l, nW);

    dim3 ggrid(DM / 128, L_SEQ / 128);   // (6, 32)

    // 2) projections (bf16 hi/lo outputs; V transposed per-head)
    gemm_mma_kernel<1><<<ggrid, 256>>>(inq_h, inq_l, wq_h, wq_l, bq, nullptr, qp_h, qp_l);
    gemm_mma_kernel<1><<<ggrid, 256>>>(ink_h, ink_l, wk_h, wk_l, bk, nullptr, kp_h, kp_l);
    gemm_mma_kernel<2><<<ggrid, 256>>>(inv_h, inv_l, wv_h, wv_l, bv, nullptr, vt_h, vt_l);

    // 3) attention
    dim3 fgrid(L_SEQ / 128, NH);
    flash_mma_kernel<<<fgrid, 256, FLASH_SMEM_BYTES>>>(
        qp_h, qp_l, kp_h, kp_l, vt_h, vt_l, att_h, att_l);

    // 4) output projection (fp32 out)
    gemm_mma_kernel<0><<<ggrid, 256>>>(att_h, att_l, wo_h, wo_l, bo, out, nullptr, nullptr);
}